// round 2
// baseline (speedup 1.0000x reference)
#include <cuda_runtime.h>
#include <cuda_bf16.h>
#include <cstdint>
#include <float.h>

// Neural CYK, n=16, R=64. Single persistent kernel, software grid barrier.
// chart[L][s][r] = max_{k,j,l} relu(W[r,j,l] * chart[k][s][j] * chart[L-k][s+k][l])
//
// Identities used (exact):
//   max_k (w * p_k) = max(w * pmax, w * pmin)          (k-split collapse)
//   max(w*pmax, w*pmin) = relu(w)*pmax + min(w,0)*pmin (sign split; one term is +-0)

#define NTOK 16
#define R 64
#define NBLK 128          // <= 148 SMs -> all blocks co-resident (barrier-safe)
#define T 512
#define C 32              // jl columns per block: 128*32 = 4096 = 64*64

__device__ float g_chart[17][NTOK][R];
__device__ unsigned g_count = 0;
__device__ volatile unsigned g_phase = 0;   // monotone across graph replays

__device__ __forceinline__ float fmax4s(float a, float b) { return fmaxf(a, b); }

__device__ __forceinline__ void grid_bar(unsigned& myph) {
    __syncthreads();
    if (threadIdx.x == 0) {
        __threadfence();                       // make REDs/stores visible
        unsigned target = myph + 1;
        unsigned prev = atomicAdd(&g_count, 1);
        if (prev == NBLK - 1) {
            g_count = 0;
            __threadfence();
            g_phase = target;                  // release
        } else {
            while (g_phase != target) { }      // acquire-spin (volatile)
        }
        __threadfence();
    }
    __syncthreads();
    myph++;
}

__global__ void __launch_bounds__(T) cyk_kernel(const int* __restrict__ tokens,
                                                const float* __restrict__ W,
                                                const float* __restrict__ E,
                                                float* __restrict__ out) {
    __shared__ float4 sA4[C][16];     // relu(W)   [jl_local][rgroup]  8KB
    __shared__ float4 sB4[C][16];     // min(W,0)                      8KB
    __shared__ float2 sP[15][C];      // (pmax, pmin) per (cell, jl)   3.75KB
    __shared__ float4 sRed[32][16];   // per-slot partial maxima       8KB

    const int t = threadIdx.x;
    const int b = blockIdx.x;
    const int j  = b >> 1;            // this block's (single) j
    const int l0 = (b & 1) * 32;      // this block's l range start

    unsigned myph = g_phase;          // snapshot before first arrive (safe)

    // ---- init: W chunk -> SMEM (sign-split), zero chart, level-1 from E ----
    {
        float* pA = (float*)sA4;
        float* pB = (float*)sB4;
        #pragma unroll
        for (int it = 0; it < 4; it++) {
            int idx = t + it * T;             // 0..2047
            int i = idx & 31;                 // jl local (fast -> coalesced LDG)
            int r = idx >> 5;                 // 0..63
            float w = W[r * 4096 + b * C + i];
            pA[i * 64 + r] = fmaxf(w, 0.0f);
            pB[i * 64 + r] = fminf(w, 0.0f);
        }
        int gid = b * T + t;
        if (gid < 15 * NTOK * R) {            // zero levels 2..16
            (&g_chart[2][0][0])[gid] = 0.0f;
        }
        if (b == NBLK - 1) {                  // level 1 = E[tokens]
            for (int idx = t; idx < NTOK * R; idx += T) {
                int s = idx >> 6, r = idx & 63;
                g_chart[1][s][r] = E[tokens[s] * R + r];
            }
        }
    }
    grid_bar(myph);

    // ---- level loop ----
    for (int L = 2; L <= NTOK; L++) {
        const int S  = NTOK - L + 1;
        const int nk = L - 1;

        // p-stats for all S cells of this level, this block's 32 jl
        if (t < 32 * S) {
            int s = t >> 5, i = t & 31;
            float pmx = -FLT_MAX, pmn = FLT_MAX;
            for (int k = 1; k <= nk; k++) {
                float u = __ldcg(&g_chart[k][s][j]);          // broadcast
                float v = __ldcg(&g_chart[L - k][s + k][l0 + i]);
                float p = u * v;
                pmx = fmaxf(pmx, p);
                pmn = fminf(pmn, p);
            }
            sP[s][i] = make_float2(pmx, pmn);
        }
        __syncthreads();

        // main: slot -> (cell, jl-subset); thread owns 4 consecutive r
        const int J = 32 / S;                 // jl-splits per cell
        const int rg = t & 15;
        const int slot = t >> 4;              // 0..31
        if (slot < S * J) {
            int s = slot / J;
            int jsub = slot - s * J;
            float4 best = make_float4(0.f, 0.f, 0.f, 0.f);   // relu floor
            for (int i = jsub; i < C; i += J) {
                float4 a  = sA4[i][rg];
                float4 bb = sB4[i][rg];
                float2 p  = sP[s][i];
                best.x = fmax4s(best.x, fmaf(a.x, p.x, bb.x * p.y));
                best.y = fmax4s(best.y, fmaf(a.y, p.x, bb.y * p.y));
                best.z = fmax4s(best.z, fmaf(a.z, p.x, bb.z * p.y));
                best.w = fmax4s(best.w, fmaf(a.w, p.x, bb.w * p.y));
            }
            sRed[slot][rg] = best;
        }
        __syncthreads();

        // reduce J jl-subsets per (cell, r), publish via atomicMax (values >= 0)
        if (t < 16 * S) {
            int rg2 = t & 15, s = t >> 4;
            float4 best = sRed[s * J][rg2];
            for (int q = 1; q < J; q++) {
                float4 x = sRed[s * J + q][rg2];
                best.x = fmaxf(best.x, x.x);
                best.y = fmaxf(best.y, x.y);
                best.z = fmaxf(best.z, x.z);
                best.w = fmaxf(best.w, x.w);
            }
            int* dst = (int*)&g_chart[L][s][rg2 * 4];
            atomicMax(dst + 0, __float_as_int(best.x));
            atomicMax(dst + 1, __float_as_int(best.y));
            atomicMax(dst + 2, __float_as_int(best.z));
            atomicMax(dst + 3, __float_as_int(best.w));
        }
        grid_bar(myph);
    }

    if (b == 0 && t == 0) {
        out[0] = __ldcg(&g_chart[NTOK][0][0]);
    }
}

extern "C" void kernel_launch(void* const* d_in, const int* in_sizes, int n_in,
                              void* d_out, int out_size) {
    const int*   tokens = (const int*)d_in[0];
    const float* W      = (const float*)d_in[1];
    const float* E      = (const float*)d_in[2];
    float*       out    = (float*)d_out;

    cyk_kernel<<<NBLK, T>>>(tokens, W, E, out);
}

// round 3
// speedup vs baseline: 1.3812x; 1.3812x over previous
#include <cuda_runtime.h>
#include <cuda_bf16.h>
#include <cstdint>
#include <float.h>

// Neural CYK, n=16, R=64, V=26.
// chart[L][s][r] = max_{k,j,l} relu(W[r,j,l] * chart[k][s][j] * chart[L-k][s+k][l])
// Exact k-collapse: max_k(w * p_k) = max(w * pmax, w * pmin),
//   pmax/pmin = max/min over k of u_k[j] * v_k[l].
// Ownership: block (s, rgroup) computes chart[L][s][rg*8 .. rg*8+7] completely.
// -> plain stores, no atomics, no cross-block reduction, no chart zeroing.

#define NTOK 16
#define RR 64

__device__ float g_chart[17][NTOK][RR];   // levels 2..16 used

__global__ void __launch_bounds__(512)
level_kernel(const int L,
             const int* __restrict__ tokens,
             const float* __restrict__ W,
             const float* __restrict__ E,
             float* __restrict__ out) {
    const int s  = blockIdx.x;        // 0 .. S-1
    const int rg = blockIdx.y;        // 0 .. 7  (8 rules each)
    const int t  = threadIdx.x;       // 0 .. 511
    const int nk = L - 1;

    __shared__ float  sU[15][RR];     // chart[k][s][:],      k=1..nk
    __shared__ float  sV[15][RR];     // chart[L-k][s+k][:]
    __shared__ float2 sP[4096];       // (pmax, pmin) per jl  (32KB)
    __shared__ float  sRed[16][8];    // per-warp partial maxima

    // ---- stage the 2*nk chart vectors (level-1 rows come straight from E) ----
    for (int i = t; i < nk * RR; i += 512) {
        int kk = i >> 6;              // 0..nk-1, k = kk+1
        int r  = i & 63;
        int k  = kk + 1;
        sU[kk][r] = (k == 1) ? E[tokens[s] * RR + r]
                             : g_chart[k][s][r];
        int Lk = L - k;
        sV[kk][r] = (Lk == 1) ? E[tokens[s + k] * RR + r]
                              : g_chart[Lk][s + k][r];
    }
    __syncthreads();

    // ---- p-stats: thread owns 8 consecutive jl (same j for all 8) ----
    {
        const int jl0 = t * 8;
        const int j   = jl0 >> 6;
        const int l0  = jl0 & 63;
        float pmx[8], pmn[8];
        #pragma unroll
        for (int i = 0; i < 8; i++) { pmx[i] = -FLT_MAX; pmn[i] = FLT_MAX; }
        for (int k = 0; k < nk; k++) {
            float u = sU[k][j];
            #pragma unroll
            for (int i = 0; i < 8; i++) {
                float p = u * sV[k][l0 + i];
                pmx[i] = fmaxf(pmx[i], p);
                pmn[i] = fminf(pmn[i], p);
            }
        }
        #pragma unroll
        for (int i = 0; i < 8; i++) sP[jl0 + i] = make_float2(pmx[i], pmn[i]);
    }
    __syncthreads();

    // ---- main: warp owns a 256-jl slice, scans all 8 r of this rgroup ----
    const int warp   = t >> 5;
    const int lane   = t & 31;
    const int jlbase = warp * 256;

    float best[8];
    #pragma unroll
    for (int q = 0; q < 8; q++) best[q] = 0.0f;   // relu floor

    #pragma unroll
    for (int it = 0; it < 2; it++) {
        const int jl = jlbase + it * 128 + lane * 4;
        const float4 pa = *(const float4*)&sP[jl];      // (p0.x p0.y p1.x p1.y)
        const float4 pb = *(const float4*)&sP[jl + 2];  // (p2.x p2.y p3.x p3.y)
        #pragma unroll
        for (int q = 0; q < 8; q++) {
            const float4 w4 = *(const float4*)(W + (size_t)(rg * 8 + q) * 4096 + jl);
            float m0 = fmaxf(w4.x * pa.x, w4.x * pa.y);
            float m1 = fmaxf(w4.y * pa.z, w4.y * pa.w);
            float m2 = fmaxf(w4.z * pb.x, w4.z * pb.y);
            float m3 = fmaxf(w4.w * pb.z, w4.w * pb.w);
            best[q] = fmaxf(best[q], fmaxf(fmaxf(m0, m1), fmaxf(m2, m3)));
        }
    }

    // ---- reduce: lanes (shfl) then warps (SMEM), plain store ----
    #pragma unroll
    for (int q = 0; q < 8; q++) {
        float b = best[q];
        #pragma unroll
        for (int off = 16; off; off >>= 1)
            b = fmaxf(b, __shfl_xor_sync(0xFFFFFFFFu, b, off));
        if (lane == 0) sRed[warp][q] = b;
    }
    __syncthreads();

    if (t < 8) {
        float b = sRed[0][t];
        #pragma unroll
        for (int w2 = 1; w2 < 16; w2++) b = fmaxf(b, sRed[w2][t]);
        g_chart[L][s][rg * 8 + t] = b;
        if (L == NTOK && s == 0 && rg == 0 && t == 0) out[0] = b;
    }
}

extern "C" void kernel_launch(void* const* d_in, const int* in_sizes, int n_in,
                              void* d_out, int out_size) {
    const int*   tokens = (const int*)d_in[0];
    const float* W      = (const float*)d_in[1];
    const float* E      = (const float*)d_in[2];
    float*       out    = (float*)d_out;

    for (int L = 2; L <= NTOK; L++) {
        dim3 grid(NTOK - L + 1, 8);
        level_kernel<<<grid, 512>>>(L, tokens, W, E, out);
    }
}

// round 4
// speedup vs baseline: 1.8934x; 1.3708x over previous
#include <cuda_runtime.h>
#include <cuda_bf16.h>
#include <cstdint>
#include <float.h>

// Neural CYK, n=16, R=64. One persistent kernel.
// chart[L][s][r] = max_{k,j,l} relu(W[r,j,l] * chart[k][s][j] * chart[L-k][s+k][l])
// Exact identities:
//   max_k (w p_k) = max(w pmax, w pmin)
//   max(w pmax, w pmin) = relu(w)*pmax + min(w,0)*pmin   (one term is +-0)
//
// 128 blocks = 32 jl-chunks (128 jl) x 4 r-groups (16 r). Each block:
//   - stages its sign-split W tile in SMEM once (whole run)
//   - keeps a full chart mirror in SMEM, refreshed with S*64 values per level
//   - combines across the 32 chunks via red.global.max (fp>=0 -> int max ok)
//   - flag-array grid barrier (parallel arrivals, single release word)

#define NTOK 16
#define RR 64
#define NBLK 128
#define T 256
#define CJL 128     // jl per chunk
#define RG 16       // rules per rgroup

__device__ float g_chart[17][NTOK][RR];
__device__ volatile unsigned g_arrive[NBLK];
__device__ volatile unsigned g_release;

// dynamic SMEM layout (bytes):
//   sChart : 17*16*64 f32          = 69632
//   sW4    : 64 jlpair * 16 r * f4 = 16384   (wp0,wn0,wp1,wn1)
//   sP     : 15 s * 128 jl * f2    = 15360   (pmax,pmin)
#define OFF_W   69632
#define OFF_P   (69632 + 16384)
#define SMEM_BYTES (OFF_P + 15360)

__device__ __forceinline__ void gbar(unsigned target) {
    __syncthreads();
    if (blockIdx.x == 0) {
        // wait for everyone else's arrival flag
        if (threadIdx.x >= 1 && threadIdx.x < NBLK) {
            while (g_arrive[threadIdx.x] < target) { }
        }
        __syncthreads();
        if (threadIdx.x == 0) {
            __threadfence();
            g_release = target;
        }
    } else {
        if (threadIdx.x == 0) {
            __threadfence();               // order REDG/STG before flag
            g_arrive[blockIdx.x] = target;
            while (g_release < target) { } // wait for release
        }
    }
    __syncthreads();
}

__global__ void __launch_bounds__(T, 1)
cyk_kernel(const int* __restrict__ tokens,
           const float* __restrict__ W,
           const float* __restrict__ E,
           float* __restrict__ out) {
    extern __shared__ char smem[];
    float  (*sChart)[NTOK][RR] = (float(*)[NTOK][RR])smem;
    float4 (*sW4)[RG]          = (float4(*)[RG])(smem + OFF_W);
    float2 (*sP)[CJL]          = (float2(*)[CJL])(smem + OFF_P);

    const int t     = threadIdx.x;
    const int b     = blockIdx.x;
    const int chunk = b >> 2;          // 0..31
    const int rg    = b & 3;           // 0..3

    const unsigned base = g_release;   // monotone across graph replays

    // ---------------- init ----------------
    // Stage sign-split W tile: sW4[jl/2][rl] = (wp,wn of jl | wp,wn of jl+1)
    for (int i = t; i < RG * CJL; i += T) {
        int rl = i >> 7;               // 0..15
        int jl = i & 127;
        float w = W[(size_t)(rg * RG + rl) * 4096 + chunk * CJL + jl];
        float2* dst = (float2*)&sW4[jl >> 1][rl];
        dst[jl & 1] = make_float2(fmaxf(w, 0.0f), fminf(w, 0.0f));
    }
    // Zero gmem chart levels 2..16 (REDG targets) — every launch.
    {
        int i = b * T + t;
        if (i < 15 * NTOK * RR) (&g_chart[2][0][0])[i] = 0.0f;
    }
    // Mirror level 1 = E[tokens] (every block, from L2)
    for (int i = t; i < NTOK * RR; i += T) {
        int s = i >> 6, r = i & 63;
        sChart[1][s][r] = E[tokens[s] * RR + r];
    }
    gbar(base + 1);

    // ---------------- level loop ----------------
    for (int L = 2; L <= NTOK; L++) {
        const int S  = NTOK + 1 - L;
        const int nk = L - 1;

        // p-stats over k for this chunk's 128 jl, all S cells (SMEM only)
        {
            const int jl = t & (CJL - 1);
            const int j  = (chunk * CJL + jl) >> 6;
            const int l  = jl & 63;
            for (int s = (t >> 7); s < S; s += 2) {
                float pmx = -FLT_MAX, pmn = FLT_MAX;
                #pragma unroll 4
                for (int k = 1; k <= nk; k++) {
                    float p = sChart[k][s][j] * sChart[L - k][s + k][l];
                    pmx = fmaxf(pmx, p);
                    pmn = fminf(pmn, p);
                }
                sP[s][jl] = make_float2(pmx, pmn);
            }
        }
        __syncthreads();

        // main: thread (rl, s) scans 128 jl from SMEM; REDG-combine
        {
            const int rl = t & 15;
            const int s  = t >> 4;
            if (s < S) {
                const float4* prow = (const float4*)&sP[s][0];
                float best = 0.0f;                       // relu floor
                #pragma unroll 8
                for (int jp = 0; jp < 64; jp++) {
                    float4 w = sW4[jp][rl];
                    float4 p = prow[jp];                 // (px0,pn0,px1,pn1)
                    best = fmaxf(best, fmaf(w.x, p.x, w.y * p.y));
                    best = fmaxf(best, fmaf(w.z, p.z, w.w * p.w));
                }
                atomicMax((int*)&g_chart[L][s][rg * RG + rl],
                          __float_as_int(best));
            }
        }
        gbar(base + L);

        // refresh mirror with this level's combined values
        for (int i = t; i < S * RR; i += T) {
            int s = i >> 6, r = i & 63;
            sChart[L][s][r] = __ldcg(&g_chart[L][s][r]);
        }
        __syncthreads();
    }

    if (b == 0 && t == 0) out[0] = sChart[NTOK][0][0];
}

extern "C" void kernel_launch(void* const* d_in, const int* in_sizes, int n_in,
                              void* d_out, int out_size) {
    const int*   tokens = (const int*)d_in[0];
    const float* W      = (const float*)d_in[1];
    const float* E      = (const float*)d_in[2];
    float*       out    = (float*)d_out;

    cudaFuncSetAttribute(cyk_kernel,
                         cudaFuncAttributeMaxDynamicSharedMemorySize,
                         SMEM_BYTES);
    cyk_kernel<<<NBLK, T, SMEM_BYTES>>>(tokens, W, E, out);
}